// round 13
// baseline (speedup 1.0000x reference)
#include <cuda_runtime.h>

typedef unsigned int u32;

#define IN_PN  20000
#define OUT_PN 5000
#define MNB    9
#define CIN    32
#define COUT   64
#define SLOT   36                 /* padded row stride (floats) */
#define TILEF  (64 * SLOT)        /* floats per 64x32 tile */
#define TB     (TILEF * 4)        /* tile bytes = 9216 */

__device__ __forceinline__ u32 tf32c(float x) {
    u32 r; asm("cvt.rna.tf32.f32 %0, %1;" : "=r"(r) : "f"(x)); return r;
}
__device__ __forceinline__ void mma8(float d[4], u32 a0, u32 a1, u32 a2, u32 a3,
                                     u32 b0, u32 b1) {
    asm("mma.sync.aligned.m16n8k8.row.col.f32.tf32.tf32.f32 "
        "{%0,%1,%2,%3}, {%4,%5,%6,%7}, {%8,%9}, {%0,%1,%2,%3};"
        : "+f"(d[0]), "+f"(d[1]), "+f"(d[2]), "+f"(d[3])
        : "r"(a0), "r"(a1), "r"(a2), "r"(a3), "r"(b0), "r"(b1));
}
__device__ __forceinline__ void ldsm4(u32 r[4], u32 addr) {
    asm volatile("ldmatrix.sync.aligned.m8n8.x4.shared.b16 {%0,%1,%2,%3}, [%4];"
                 : "=r"(r[0]), "=r"(r[1]), "=r"(r[2]), "=r"(r[3]) : "r"(addr));
}
__device__ __forceinline__ void cpasync16(u32 dst, const float* src) {
    asm volatile("cp.async.cg.shared.global [%0], [%1], 16;" :: "r"(dst), "l"(src));
}
__device__ __forceinline__ void cpasync16z(u32 dst, const float* src, u32 src_bytes) {
    asm volatile("cp.async.cg.shared.global [%0], [%1], 16, %2;"
                 :: "r"(dst), "l"(src), "r"(src_bytes));
}
__device__ __forceinline__ void cpcommit() {
    asm volatile("cp.async.commit_group;" ::: "memory");
}
__device__ __forceinline__ void cpwait0() {
    asm volatile("cp.async.wait_group 0;" ::: "memory");
}

// one 64x64x32 slice for this warp's 32b x 32o tile. Both operands raw fp32:
// tf32 MMA truncates low 13 bits; bias (1+2^-11 ln2)^2 corrected in epilogue.
// rna-staged tiles (rs / wres) are already tf32 -> truncation is identity.
__device__ __forceinline__ void slice_mma(u32 aA0, u32 aA1, u32 wA,
                                          float acc[2][4][4])
{
    #pragma unroll
    for (int kk = 0; kk < 4; kk++) {
        u32 a0[4], a1[4], w0[4], w1[4];
        ldsm4(a0, aA0); ldsm4(a1, aA1);
        ldsm4(w0, wA);  ldsm4(w1, wA + 16);
        aA0 += 32; aA1 += 32; wA += 32;
        #pragma unroll
        for (int j = 0; j < 4; j++) {
            mma8(acc[0][j], a0[0], a0[1], a0[2], a0[3], w0[j], w1[j]);
            mma8(acc[1][j], a1[0], a1[1], a1[2], a1[3], w0[j], w1[j]);
        }
    }
}

__device__ __forceinline__ void ldg16(float v[16], const float* __restrict__ src) {
    #pragma unroll
    for (int j = 0; j < 4; j++) {
        float4 a = ((const float4*)src)[j];
        v[4*j+0] = a.x; v[4*j+1] = a.y; v[4*j+2] = a.z; v[4*j+3] = a.w;
    }
}
__device__ __forceinline__ void sts16(float* dst, const float v[16], float sc) {
    #pragma unroll
    for (int j = 0; j < 4; j++) {
        uint4 x;
        x.x = tf32c(v[4*j+0] * sc); x.y = tf32c(v[4*j+1] * sc);
        x.z = tf32c(v[4*j+2] * sc); x.w = tf32c(v[4*j+3] * sc);
        ((uint4*)dst)[j] = x;
    }
}

// stage one slice: W (8KB seq) + gathered In (8KB random) into tile pair `buf`
__device__ __forceinline__ void stage(const float* __restrict__ wslice,
                                      const float* __restrict__ inrow,
                                      int nv, u32 smb, u32 buf, u32 stOff)
{
    u32 wdst = smb + 2u * TB + buf + stOff;
    #pragma unroll
    for (int j = 0; j < 4; j++) cpasync16(wdst + 16u * j, wslice + 4 * j);

    const float* isrc = inrow + (size_t)((nv == IN_PN) ? 0 : nv) * CIN;
    u32 sb = (nv == IN_PN) ? 0u : 16u;
    u32 adst = smb + buf + stOff;
    #pragma unroll
    for (int j = 0; j < 4; j++) cpasync16z(adst + 16u * j, isrc + 4 * j, sb);
    cpcommit();
}

#define PPC 2   /* points per CTA */

__global__ __launch_bounds__(128, 6)
void pconv_mma(const float* __restrict__ in_pc,
               const int*   __restrict__ nid_g,
               const float* __restrict__ wts,
               const float* __restrict__ bias,
               const float* __restrict__ pnb,
               const float* __restrict__ wres,
               float* __restrict__ out)
{
    // layout: A0 @0, A1 @TILEF, W0 @2*TILEF, W1 @3*TILEF, header after
    __shared__ float sm[4 * TILEF + 64];
    float* pm_s  = sm + 4 * TILEF;            // [2][16]
    int*   nid_s = (int*)(sm + 4 * TILEF + 32); // [2][16]

    const int tid  = threadIdx.x;
    const int lane = tid & 31;
    const int wid  = tid >> 5;
    const int pbase = blockIdx.x * PPC;

    const int bg  = (wid >> 1) * 32;
    const int og  = (wid & 1) * 32;
    const int g   = lane >> 2;
    const int tig = lane & 3;

    const int srow = tid >> 1;
    const int scol = (tid & 1) * 16;

    // header: both points' neighbor ids + masked |p| weights
    if (tid < PPC * 16) {
        int pt = tid >> 4, m = tid & 15;
        if (m < MNB) {
            int nv = nid_g[(pbase + pt) * MNB + m];
            nid_s[pt * 16 + m] = nv;
            pm_s[pt * 16 + m] = (nv != IN_PN) ? fabsf(pnb[(pbase + pt) * MNB + m]) : 0.0f;
        }
    }
    __syncthreads();
    if (tid < PPC) {
        float s = 1e-8f;
        #pragma unroll
        for (int m = 0; m < MNB; m++) s += pm_s[tid * 16 + m];
        float inv = 1.0f / s;
        #pragma unroll
        for (int m = 0; m < MNB; m++) pm_s[tid * 16 + m] *= inv;
    }
    __syncthreads();

    const float* inrow = in_pc + (size_t)srow * (IN_PN * CIN) + scol;
    const u32 smb = (u32)__cvta_generic_to_shared(sm);

    const u32 aFrag = smb + (u32)(bg + (lane & 15)) * (SLOT * 4u) + (u32)(lane >> 4) * 16u;
    const u32 wFrag = smb + (u32)(2 * TB) + (u32)(og + lane) * (SLOT * 4u);
    const u32 aHalf = 16u * SLOT * 4u;
    const u32 stOff = (u32)(srow * SLOT + scol) * 4u;

    const float C     = 0.70710678118654752f;   // sqrt(0.5)
    const float CORR2 = 1.000676f;               // (1 + 2^-11 ln2)^2

    // ---- prologue for point 0 only ----
    {
        const float* wsl0 = wts + (size_t)pbase * (MNB * CIN * COUT)
                          + (size_t)srow * CIN + scol;
        stage(wsl0, inrow, nid_s[0], smb, 0u, stOff);
        cpwait0();
    }
    __syncthreads();

    #pragma unroll 1
    for (int pt = 0; pt < PPC; pt++) {
        const int p = pbase + pt;
        const float* wsl  = wts + (size_t)p * (MNB * CIN * COUT)
                          + (size_t)srow * CIN + scol;
        const float* pmp  = pm_s + pt * 16;
        const int*   nidp = nid_s + pt * 16;

        float rs[16];
        #pragma unroll
        for (int i = 0; i < 16; i++) rs[i] = 0.0f;

        float acc[2][4][4];
        #pragma unroll
        for (int b = 0; b < 2; b++)
            #pragma unroll
            for (int j = 0; j < 4; j++)
                #pragma unroll
                for (int e = 0; e < 4; e++) acc[b][j][e] = 0.0f;

        // ---- main loop: 2-stage double buffer (slice m in buf m&1) ----
        #pragma unroll 1
        for (int m = 0; m < MNB; m++) {
            const u32 cOff = (m & 1) ? (u32)TB : 0u;
            const u32 nOff = (u32)TB - cOff;

            if (m < MNB - 1)
                stage(wsl + (size_t)(m + 1) * (CIN * COUT), inrow, nidp[m + 1],
                      smb, nOff, stOff);

            slice_mma(aFrag + cOff, aFrag + cOff + aHalf, wFrag + cOff, acc);

            // residual pre-reduction from the current landed A tile
            {
                const float* at = sm + (cOff >> 2) + srow * SLOT + scol;
                const float pmv = pmp[m];
                #pragma unroll
                for (int j = 0; j < 4; j++) {
                    float4 q = ((const float4*)at)[j];
                    rs[4*j+0] = fmaf(pmv, q.x, rs[4*j+0]);
                    rs[4*j+1] = fmaf(pmv, q.y, rs[4*j+1]);
                    rs[4*j+2] = fmaf(pmv, q.z, rs[4*j+2]);
                    rs[4*j+3] = fmaf(pmv, q.w, rs[4*j+3]);
                }
            }

            if (m < MNB - 1) {
                cpwait0();
                __syncthreads();
            }
        }

        // buf0 consumed by m=8; buf1 free since m=7. Sync, then kick off the
        // NEXT point's slice-0 stage into buf0 so its gather latency hides
        // under this point's residual + epilogue.
        __syncthreads();
        if (pt + 1 < PPC) {
            const float* wsln = wts + (size_t)(p + 1) * (MNB * CIN * COUT)
                              + (size_t)srow * CIN + scol;
            stage(wsln, inrow, nid_s[(pt + 1) * 16], smb, 0u, stOff);
        }

        // residual operands into buf1 (A1 <- rs, W1 <- sqrt(RR)*wres), rna cvt
        sts16(sm + TILEF + srow * SLOT + scol, rs, 1.0f);
        {
            float vw[16];
            ldg16(vw, wres + (size_t)srow * CIN + scol);
            sts16(sm + 3 * TILEF + srow * SLOT + scol, vw, C);
        }

        // acc <- C * elu(CORR2*acc + bias)
        const float* brow = bias + (size_t)p * COUT;
        #pragma unroll
        for (int j = 0; j < 4; j++) {
            const int o0 = og + 8 * j + 2 * tig;
            float2 bb = *(const float2*)(brow + o0);
            #pragma unroll
            for (int b = 0; b < 2; b++) {
                float x0 = fmaf(acc[b][j][0], CORR2, bb.x);
                float x1 = fmaf(acc[b][j][1], CORR2, bb.y);
                float x2 = fmaf(acc[b][j][2], CORR2, bb.x);
                float x3 = fmaf(acc[b][j][3], CORR2, bb.y);
                x0 = (x0 > 0.0f) ? x0 : expm1f(x0);
                x1 = (x1 > 0.0f) ? x1 : expm1f(x1);
                x2 = (x2 > 0.0f) ? x2 : expm1f(x2);
                x3 = (x3 > 0.0f) ? x3 : expm1f(x3);
                acc[b][j][0] = C * x0; acc[b][j][1] = C * x1;
                acc[b][j][2] = C * x2; acc[b][j][3] = C * x3;
            }
        }
        __syncthreads();

        // residual MMA accumulates in place (buf1; both operands rna tf32)
        slice_mma(aFrag + TB, aFrag + TB + aHalf, wFrag + TB, acc);

        // store: out[b][p][o]
        #pragma unroll
        for (int j = 0; j < 4; j++) {
            const int o0 = og + 8 * j + 2 * tig;
            #pragma unroll
            for (int b = 0; b < 2; b++) {
                const int r0 = bg + 16 * b + g;
                float2 v0 = { acc[b][j][0], acc[b][j][1] };
                float2 v1 = { acc[b][j][2], acc[b][j][3] };
                *(float2*)(out + ((size_t)r0       * OUT_PN + p) * COUT + o0) = v0;
                *(float2*)(out + ((size_t)(r0 + 8) * OUT_PN + p) * COUT + o0) = v1;
            }
        }

        // order: all warps past residual-mma reads of buf1, and next point's
        // slice-0 landed in buf0, before the next iteration stages into buf1.
        if (pt + 1 < PPC) {
            cpwait0();
            __syncthreads();
        }
    }
}

extern "C" void kernel_launch(void* const* d_in, const int* in_sizes, int n_in,
                              void* d_out, int out_size)
{
    const float* in_pc = (const float*)d_in[0];
    const int*   nid   = (const int*)  d_in[1];
    const float* wts   = (const float*)d_in[2];
    const float* bias  = (const float*)d_in[3];
    const float* pnb   = (const float*)d_in[4];
    const float* wres  = (const float*)d_in[5];
    float* out = (float*)d_out;

    pconv_mma<<<OUT_PN / PPC, 128>>>(in_pc, nid, wts, bias, pnb, wres, out);
}

// round 15
// speedup vs baseline: 1.0838x; 1.0838x over previous
#include <cuda_runtime.h>

typedef unsigned int u32;

#define IN_PN  20000
#define OUT_PN 5000
#define MNB    9
#define CIN    32
#define COUT   64
#define SLOT   36                 /* padded row stride (floats) */
#define TILEF  (64 * SLOT)        /* floats per 64x32 tile */
#define TB     (TILEF * 4)        /* tile bytes = 9216 */

__device__ __forceinline__ u32 tf32c(float x) {
    u32 r; asm("cvt.rna.tf32.f32 %0, %1;" : "=r"(r) : "f"(x)); return r;
}
__device__ __forceinline__ void mma8(float d[4], u32 a0, u32 a1, u32 a2, u32 a3,
                                     u32 b0, u32 b1) {
    asm("mma.sync.aligned.m16n8k8.row.col.f32.tf32.tf32.f32 "
        "{%0,%1,%2,%3}, {%4,%5,%6,%7}, {%8,%9}, {%0,%1,%2,%3};"
        : "+f"(d[0]), "+f"(d[1]), "+f"(d[2]), "+f"(d[3])
        : "r"(a0), "r"(a1), "r"(a2), "r"(a3), "r"(b0), "r"(b1));
}
__device__ __forceinline__ void ldsm4(u32 r[4], u32 addr) {
    asm volatile("ldmatrix.sync.aligned.m8n8.x4.shared.b16 {%0,%1,%2,%3}, [%4];"
                 : "=r"(r[0]), "=r"(r[1]), "=r"(r[2]), "=r"(r[3]) : "r"(addr));
}
__device__ __forceinline__ void cpasync16z(u32 dst, const float* src, u32 src_bytes) {
    asm volatile("cp.async.cg.shared.global [%0], [%1], 16, %2;"
                 :: "r"(dst), "l"(src), "r"(src_bytes));
}
__device__ __forceinline__ void cpcommit() {
    asm volatile("cp.async.commit_group;" ::: "memory");
}
__device__ __forceinline__ void cpwait0() {
    asm volatile("cp.async.wait_group 0;" ::: "memory");
}

// one 64x64x32 slice for this warp's 32b x 32o tile. Both operands raw fp32:
// tf32 MMA truncates low 13 bits; bias (1+2^-11 ln2)^2 corrected in epilogue.
// rna-staged tiles (rs / wres) are already tf32 -> truncation is identity.
__device__ __forceinline__ void slice_mma(u32 aA0, u32 aA1, u32 wA,
                                          float acc[2][4][4])
{
    #pragma unroll
    for (int kk = 0; kk < 4; kk++) {
        u32 a0[4], a1[4], w0[4], w1[4];
        ldsm4(a0, aA0); ldsm4(a1, aA1);
        ldsm4(w0, wA);  ldsm4(w1, wA + 16);
        aA0 += 32; aA1 += 32; wA += 32;
        #pragma unroll
        for (int j = 0; j < 4; j++) {
            mma8(acc[0][j], a0[0], a0[1], a0[2], a0[3], w0[j], w1[j]);
            mma8(acc[1][j], a1[0], a1[1], a1[2], a1[3], w0[j], w1[j]);
        }
    }
}

// streaming (evict-first) 16-float global load
__device__ __forceinline__ void ldg16cs(float4 v[4], const float* __restrict__ src) {
    #pragma unroll
    for (int j = 0; j < 4; j++) v[j] = __ldcs(((const float4*)src) + j);
}
// raw 16-float STS (no cvt — W consumed as raw fp32 by the truncating MMA)
__device__ __forceinline__ void stsraw16(float* dst, const float4 v[4]) {
    #pragma unroll
    for (int j = 0; j < 4; j++) ((float4*)dst)[j] = v[j];
}
__device__ __forceinline__ void ldg16(float v[16], const float* __restrict__ src) {
    #pragma unroll
    for (int j = 0; j < 4; j++) {
        float4 a = ((const float4*)src)[j];
        v[4*j+0] = a.x; v[4*j+1] = a.y; v[4*j+2] = a.z; v[4*j+3] = a.w;
    }
}
__device__ __forceinline__ void sts16(float* dst, const float v[16], float sc) {
    #pragma unroll
    for (int j = 0; j < 4; j++) {
        uint4 x;
        x.x = tf32c(v[4*j+0] * sc); x.y = tf32c(v[4*j+1] * sc);
        x.z = tf32c(v[4*j+2] * sc); x.w = tf32c(v[4*j+3] * sc);
        ((uint4*)dst)[j] = x;
    }
}

__global__ __launch_bounds__(128, 5)
void pconv_mma(const float* __restrict__ in_pc,
               const int*   __restrict__ nid_g,
               const float* __restrict__ wts,
               const float* __restrict__ bias,
               const float* __restrict__ pnb,
               const float* __restrict__ wres,
               float* __restrict__ out)
{
    // layout: A0 @0, A1 @TILEF, W0 @2*TILEF, W1 @3*TILEF
    __shared__ float sm[4 * TILEF + 32];
    float* pm_s  = sm + 4 * TILEF;
    int*   nid_s = (int*)(sm + 4 * TILEF + 16);

    const int tid  = threadIdx.x;
    const int lane = tid & 31;
    const int wid  = tid >> 5;
    const int p    = blockIdx.x;

    const int bg  = (wid >> 1) * 32;
    const int og  = (wid & 1) * 32;
    const int g   = lane >> 2;
    const int tig = lane & 3;

    const int srow = tid >> 1;
    const int scol = (tid & 1) * 16;

    if (tid < MNB) {
        int nv = nid_g[p * MNB + tid];
        nid_s[tid] = nv;
        pm_s[tid] = (nv != IN_PN) ? fabsf(pnb[p * MNB + tid]) : 0.0f;
    }
    __syncthreads();
    if (tid == 0) {
        float s = 1e-8f;
        #pragma unroll
        for (int m = 0; m < MNB; m++) s += pm_s[m];
        float inv = 1.0f / s;
        #pragma unroll
        for (int m = 0; m < MNB; m++) pm_s[m] *= inv;
    }
    __syncthreads();

    const float* wp    = wts + (size_t)p * (MNB * CIN * COUT)
                       + (size_t)srow * CIN + scol;     // per-thread W src
    const float* inrow = in_pc + (size_t)srow * (IN_PN * CIN) + scol;
    const u32 smb = (u32)__cvta_generic_to_shared(sm);

    // ldmatrix lane addresses (within A0 / W0 tiles) — verified mapping
    const u32 aFrag = smb + (u32)(bg + (lane & 15)) * (SLOT * 4u) + (u32)(lane >> 4) * 16u;
    const u32 wFrag = smb + (u32)(2 * TB) + (u32)(og + lane) * (SLOT * 4u);
    const u32 aHalf = 16u * SLOT * 4u;
    const u32 stOff = (u32)(srow * SLOT + scol) * 4u;
    float* const stW = sm + 2 * TILEF + srow * SLOT + scol;   // W staging dst (buf0)
    float* const stA = sm + srow * SLOT + scol;               // A staging dst (buf0)

    float rs[16];
    #pragma unroll
    for (int i = 0; i < 16; i++) rs[i] = 0.0f;

    float4 vw[4];

    // ---- prologue: stage slice 0 (W streaming LDG->STS, In cp.async zfill) ----
    {
        ldg16cs(vw, wp);
        int nv = nid_s[0];
        const float* isrc = inrow + (size_t)((nv == IN_PN) ? 0 : nv) * CIN;
        u32 sb = (nv == IN_PN) ? 0u : 16u;
        #pragma unroll
        for (int j = 0; j < 4; j++) cpasync16z(smb + stOff + 16u * j, isrc + 4 * j, sb);
        cpcommit();
        stsraw16(stW, vw);
        cpwait0();
    }
    __syncthreads();

    float acc[2][4][4];
    #pragma unroll
    for (int b = 0; b < 2; b++)
        #pragma unroll
        for (int j = 0; j < 4; j++)
            #pragma unroll
            for (int e = 0; e < 4; e++) acc[b][j][e] = 0.0f;

    #pragma unroll 1
    for (int m = 0; m < MNB; m++) {
        const u32 cOff = (m & 1) ? (u32)TB : 0u;   // current tile byte offset
        const u32 nOff = (u32)TB - cOff;           // next tile byte offset

        if (m < MNB - 1) {
            // W(m+1): streaming load into regs (latency hides under slice_mma)
            ldg16cs(vw, wp + (size_t)(m + 1) * (CIN * COUT));
            // In(m+1): cp.async gather with zfill
            int nv = nid_s[m + 1];
            const float* isrc = inrow + (size_t)((nv == IN_PN) ? 0 : nv) * CIN;
            u32 sb = (nv == IN_PN) ? 0u : 16u;
            #pragma unroll
            for (int j = 0; j < 4; j++)
                cpasync16z(smb + nOff + stOff + 16u * j, isrc + 4 * j, sb);
            cpcommit();
        }

        slice_mma(aFrag + cOff, aFrag + cOff + aHalf, wFrag + cOff, acc);

        // residual pre-reduction from the CURRENT landed A tile (raw fp32)
        {
            const float* at = sm + (cOff >> 2) + srow * SLOT + scol;
            const float pmv = pm_s[m];
            #pragma unroll
            for (int j = 0; j < 4; j++) {
                float4 q = ((const float4*)at)[j];
                rs[4*j+0] = fmaf(pmv, q.x, rs[4*j+0]);
                rs[4*j+1] = fmaf(pmv, q.y, rs[4*j+1]);
                rs[4*j+2] = fmaf(pmv, q.z, rs[4*j+2]);
                rs[4*j+3] = fmaf(pmv, q.w, rs[4*j+3]);
            }
        }

        if (m < MNB - 1) {
            stsraw16((float*)((char*)stW + nOff), vw);
            cpwait0();
            __syncthreads();
        }
    }

    // ---- residual slice into freed buffers A1/W1 (last slice used A0/W0) ----
    const float C = 0.70710678118654752f;   // sqrt(0.5)
    sts16(sm + TILEF + srow * SLOT + scol, rs, 1.0f);   // rna cvt: unbiased
    {
        float vwr[16];
        ldg16(vwr, wres + (size_t)srow * CIN + scol);
        sts16(sm + 3 * TILEF + srow * SLOT + scol, vwr, C);  // sqrt(RR)*wres, rna
    }

    // acc <- C * elu(CORR2*acc + bias)
    // CORR2 = (1 + 2^-11*ln2)^2 cancels truncation bias on BOTH tf32 operands
    const float CORR2 = 1.000676f;
    const float* brow = bias + (size_t)p * COUT;
    #pragma unroll
    for (int j = 0; j < 4; j++) {
        const int o0 = og + 8 * j + 2 * tig;
        float2 bb = *(const float2*)(brow + o0);
        #pragma unroll
        for (int b = 0; b < 2; b++) {
            float x0 = fmaf(acc[b][j][0], CORR2, bb.x);
            float x1 = fmaf(acc[b][j][1], CORR2, bb.y);
            float x2 = fmaf(acc[b][j][2], CORR2, bb.x);
            float x3 = fmaf(acc[b][j][3], CORR2, bb.y);
            x0 = (x0 > 0.0f) ? x0 : expm1f(x0);
            x1 = (x1 > 0.0f) ? x1 : expm1f(x1);
            x2 = (x2 > 0.0f) ? x2 : expm1f(x2);
            x3 = (x3 > 0.0f) ? x3 : expm1f(x3);
            acc[b][j][0] = C * x0; acc[b][j][1] = C * x1;
            acc[b][j][2] = C * x2; acc[b][j][3] = C * x3;
        }
    }
    __syncthreads();

    // residual MMA accumulates in place (A1/W1 both rna tf32 — unbiased)
    slice_mma(aFrag + TB, aFrag + TB + aHalf, wFrag + TB, acc);

    // ---- store: out[b][p][o] with streaming stores (st.global.cs) ----
    #pragma unroll
    for (int j = 0; j < 4; j++) {
        const int o0 = og + 8 * j + 2 * tig;
        #pragma unroll
        for (int b = 0; b < 2; b++) {
            const int r0 = bg + 16 * b + g;
            float2 v0 = { acc[b][j][0], acc[b][j][1] };
            float2 v1 = { acc[b][j][2], acc[b][j][3] };
            __stcs((float2*)(out + ((size_t)r0       * OUT_PN + p) * COUT + o0), v0);
            __stcs((float2*)(out + ((size_t)(r0 + 8) * OUT_PN + p) * COUT + o0), v1);
        }
    }
}

extern "C" void kernel_launch(void* const* d_in, const int* in_sizes, int n_in,
                              void* d_out, int out_size)
{
    const float* in_pc = (const float*)d_in[0];
    const int*   nid   = (const int*)  d_in[1];
    const float* wts   = (const float*)d_in[2];
    const float* bias  = (const float*)d_in[3];
    const float* pnb   = (const float*)d_in[4];
    const float* wres  = (const float*)d_in[5];
    float* out = (float*)d_out;

    pconv_mma<<<OUT_PN, 128>>>(in_pc, nid, wts, bias, pnb, wres, out);
}

// round 16
// speedup vs baseline: 1.0842x; 1.0004x over previous
#include <cuda_runtime.h>

typedef unsigned int u32;

#define IN_PN  20000
#define OUT_PN 5000
#define MNB    9
#define CIN    32
#define COUT   64
#define SLOT   36                 /* padded row stride (floats) */
#define TILEF  (64 * SLOT)        /* floats per 64x32 tile */
#define TB     (TILEF * 4)        /* tile bytes = 9216 */

__device__ __forceinline__ u32 tf32c(float x) {
    u32 r; asm("cvt.rna.tf32.f32 %0, %1;" : "=r"(r) : "f"(x)); return r;
}
__device__ __forceinline__ void mma8(float d[4], u32 a0, u32 a1, u32 a2, u32 a3,
                                     u32 b0, u32 b1) {
    asm("mma.sync.aligned.m16n8k8.row.col.f32.tf32.tf32.f32 "
        "{%0,%1,%2,%3}, {%4,%5,%6,%7}, {%8,%9}, {%0,%1,%2,%3};"
        : "+f"(d[0]), "+f"(d[1]), "+f"(d[2]), "+f"(d[3])
        : "r"(a0), "r"(a1), "r"(a2), "r"(a3), "r"(b0), "r"(b1));
}
__device__ __forceinline__ void ldsm4(u32 r[4], u32 addr) {
    asm volatile("ldmatrix.sync.aligned.m8n8.x4.shared.b16 {%0,%1,%2,%3}, [%4];"
                 : "=r"(r[0]), "=r"(r[1]), "=r"(r[2]), "=r"(r[3]) : "r"(addr));
}
__device__ __forceinline__ void cpasync16z(u32 dst, const float* src, u32 src_bytes) {
    asm volatile("cp.async.cg.shared.global [%0], [%1], 16, %2;"
                 :: "r"(dst), "l"(src), "r"(src_bytes));
}
__device__ __forceinline__ void cpcommit() {
    asm volatile("cp.async.commit_group;" ::: "memory");
}
__device__ __forceinline__ void cpwait0() {
    asm volatile("cp.async.wait_group 0;" ::: "memory");
}

// Main slice + fused residual rank-update.
// Main: both operands raw fp32 (tf32 MMA truncates; bias corrected at epilogue).
// Residual: D2 += A_half x (pm * I8) per kk, with the identity B-fragment
// synthesized in registers (bi0/bi1) — zero extra smem reads.
__device__ __forceinline__ void slice_mma_r(u32 aA0, u32 aA1, u32 wA,
                                            float acc[2][4][4],
                                            float acc2[4][4],
                                            u32 bi0, u32 bi1, int use_a1)
{
    #pragma unroll
    for (int kk = 0; kk < 4; kk++) {
        u32 a0[4], a1[4], w0[4], w1[4];
        ldsm4(a0, aA0); ldsm4(a1, aA1);
        ldsm4(w0, wA);  ldsm4(w1, wA + 16);
        aA0 += 32; aA1 += 32; wA += 32;
        #pragma unroll
        for (int j = 0; j < 4; j++) {
            mma8(acc[0][j], a0[0], a0[1], a0[2], a0[3], w0[j], w1[j]);
            mma8(acc[1][j], a1[0], a1[1], a1[2], a1[3], w0[j], w1[j]);
        }
        if (use_a1) mma8(acc2[kk], a1[0], a1[1], a1[2], a1[3], bi0, bi1);
        else        mma8(acc2[kk], a0[0], a0[1], a0[2], a0[3], bi0, bi1);
    }
}

// plain slice (for the final residual GEMM)
__device__ __forceinline__ void slice_mma(u32 aA0, u32 aA1, u32 wA,
                                          float acc[2][4][4])
{
    #pragma unroll
    for (int kk = 0; kk < 4; kk++) {
        u32 a0[4], a1[4], w0[4], w1[4];
        ldsm4(a0, aA0); ldsm4(a1, aA1);
        ldsm4(w0, wA);  ldsm4(w1, wA + 16);
        aA0 += 32; aA1 += 32; wA += 32;
        #pragma unroll
        for (int j = 0; j < 4; j++) {
            mma8(acc[0][j], a0[0], a0[1], a0[2], a0[3], w0[j], w1[j]);
            mma8(acc[1][j], a1[0], a1[1], a1[2], a1[3], w0[j], w1[j]);
        }
    }
}

// streaming (evict-first) 16-float global load
__device__ __forceinline__ void ldg16cs(float4 v[4], const float* __restrict__ src) {
    #pragma unroll
    for (int j = 0; j < 4; j++) v[j] = __ldcs(((const float4*)src) + j);
}
__device__ __forceinline__ void stsraw16(float* dst, const float4 v[4]) {
    #pragma unroll
    for (int j = 0; j < 4; j++) ((float4*)dst)[j] = v[j];
}
__device__ __forceinline__ void ldg16(float v[16], const float* __restrict__ src) {
    #pragma unroll
    for (int j = 0; j < 4; j++) {
        float4 a = ((const float4*)src)[j];
        v[4*j+0] = a.x; v[4*j+1] = a.y; v[4*j+2] = a.z; v[4*j+3] = a.w;
    }
}
__device__ __forceinline__ void sts16(float* dst, const float v[16], float sc) {
    #pragma unroll
    for (int j = 0; j < 4; j++) {
        uint4 x;
        x.x = tf32c(v[4*j+0] * sc); x.y = tf32c(v[4*j+1] * sc);
        x.z = tf32c(v[4*j+2] * sc); x.w = tf32c(v[4*j+3] * sc);
        ((uint4*)dst)[j] = x;
    }
}

__global__ __launch_bounds__(128, 5)
void pconv_mma(const float* __restrict__ in_pc,
               const int*   __restrict__ nid_g,
               const float* __restrict__ wts,
               const float* __restrict__ bias,
               const float* __restrict__ pnb,
               const float* __restrict__ wres,
               float* __restrict__ out)
{
    // layout: A0 @0, A1 @TILEF, W0 @2*TILEF, W1 @3*TILEF
    __shared__ float sm[4 * TILEF + 32];
    float* pm_s  = sm + 4 * TILEF;
    int*   nid_s = (int*)(sm + 4 * TILEF + 16);

    const int tid  = threadIdx.x;
    const int lane = tid & 31;
    const int wid  = tid >> 5;
    const int p    = blockIdx.x;

    const int bg  = (wid >> 1) * 32;
    const int og  = (wid & 1) * 32;
    const int g   = lane >> 2;
    const int tig = lane & 3;

    const int srow = tid >> 1;
    const int scol = (tid & 1) * 16;

    // identity-fragment predicates (b0: n==k, b1: n==k+4 within 8x8)
    const bool ip0 = (lane >> 2) == (lane & 3);
    const bool ip1 = (lane >> 2) == ((lane & 3) + 4);

    if (tid < MNB) {
        int nv = nid_g[p * MNB + tid];
        nid_s[tid] = nv;
        pm_s[tid] = (nv != IN_PN) ? fabsf(pnb[p * MNB + tid]) : 0.0f;
    }
    __syncthreads();
    if (tid == 0) {
        float s = 1e-8f;
        #pragma unroll
        for (int m = 0; m < MNB; m++) s += pm_s[m];
        float inv = 1.0f / s;
        #pragma unroll
        for (int m = 0; m < MNB; m++) pm_s[m] *= inv;
    }
    __syncthreads();

    const float* wp    = wts + (size_t)p * (MNB * CIN * COUT)
                       + (size_t)srow * CIN + scol;     // per-thread W src
    const float* inrow = in_pc + (size_t)srow * (IN_PN * CIN) + scol;
    const u32 smb = (u32)__cvta_generic_to_shared(sm);

    // ldmatrix lane addresses (within A0 / W0 tiles) — verified mapping
    const u32 aFrag = smb + (u32)(bg + (lane & 15)) * (SLOT * 4u) + (u32)(lane >> 4) * 16u;
    const u32 wFrag = smb + (u32)(2 * TB) + (u32)(og + lane) * (SLOT * 4u);
    const u32 aHalf = 16u * SLOT * 4u;
    const u32 stOff = (u32)(srow * SLOT + scol) * 4u;
    float* const stW = sm + 2 * TILEF + srow * SLOT + scol;   // W staging dst (buf0)

    float4 vw[4];

    // ---- prologue: stage slice 0 (W streaming LDG->STS, In cp.async zfill) ----
    {
        ldg16cs(vw, wp);
        int nv = nid_s[0];
        const float* isrc = inrow + (size_t)((nv == IN_PN) ? 0 : nv) * CIN;
        u32 sb = (nv == IN_PN) ? 0u : 16u;
        #pragma unroll
        for (int j = 0; j < 4; j++) cpasync16z(smb + stOff + 16u * j, isrc + 4 * j, sb);
        cpcommit();
        stsraw16(stW, vw);
        cpwait0();
    }
    __syncthreads();

    float acc[2][4][4];
    #pragma unroll
    for (int b = 0; b < 2; b++)
        #pragma unroll
        for (int j = 0; j < 4; j++)
            #pragma unroll
            for (int e = 0; e < 4; e++) acc[b][j][e] = 0.0f;

    float acc2[4][4];     // D2 = sum_m pm*In_m, this warp's 16-row b-slice
    #pragma unroll
    for (int j = 0; j < 4; j++)
        #pragma unroll
        for (int e = 0; e < 4; e++) acc2[j][e] = 0.0f;

    const int use_a1 = wid & 1;   // warps 1,3 own the upper 16 rows of their block

    #pragma unroll 1
    for (int m = 0; m < MNB; m++) {
        const u32 cOff = (m & 1) ? (u32)TB : 0u;   // current tile byte offset
        const u32 nOff = (u32)TB - cOff;           // next tile byte offset

        if (m < MNB - 1) {
            // W(m+1): streaming load into regs (latency hides under slice_mma)
            ldg16cs(vw, wp + (size_t)(m + 1) * (CIN * COUT));
            // In(m+1): cp.async gather with zfill
            int nv = nid_s[m + 1];
            const float* isrc = inrow + (size_t)((nv == IN_PN) ? 0 : nv) * CIN;
            u32 sb = (nv == IN_PN) ? 0u : 16u;
            #pragma unroll
            for (int j = 0; j < 4; j++)
                cpasync16z(smb + nOff + stOff + 16u * j, isrc + 4 * j, sb);
            cpcommit();
        }

        // identity B-fragment for this slice: pm (rna tf32, unbiased) on diag
        u32 pmbits = tf32c(pm_s[m]);
        u32 bi0 = ip0 ? pmbits : 0u;
        u32 bi1 = ip1 ? pmbits : 0u;

        slice_mma_r(aFrag + cOff, aFrag + cOff + aHalf, wFrag + cOff,
                    acc, acc2, bi0, bi1, use_a1);

        if (m < MNB - 1) {
            stsraw16((float*)((char*)stW + nOff), vw);
            cpwait0();
            __syncthreads();
        }
    }

    // ---- residual slice into freed buffers A1/W1 (last slice used A0/W0) ----
    const float C     = 0.70710678118654752f;   // sqrt(0.5)
    const float CORR1 = 1.000338f;               // A-side truncation debias (D2)
    const float CORR2 = 1.000676f;               // both-sides debias (main conv)

    // A1 <- rs from acc2: row = 16*wid + (l>>2)(+8), col = 8*kk + 2*(l&3)
    {
        float* rbase = sm + TILEF + (16 * wid + (lane >> 2)) * SLOT + 2 * (lane & 3);
        #pragma unroll
        for (int kk = 0; kk < 4; kk++) {
            uint2 lo = { tf32c(acc2[kk][0] * CORR1), tf32c(acc2[kk][1] * CORR1) };
            uint2 hi = { tf32c(acc2[kk][2] * CORR1), tf32c(acc2[kk][3] * CORR1) };
            *(uint2*)(rbase + 8 * kk)             = lo;
            *(uint2*)(rbase + 8 * kk + 8 * SLOT)  = hi;
        }
    }
    {
        float vwr[16];
        ldg16(vwr, wres + (size_t)srow * CIN + scol);
        sts16(sm + 3 * TILEF + srow * SLOT + scol, vwr, C);  // sqrt(RR)*wres, rna
    }

    // acc <- C * elu(CORR2*acc + bias)
    const float* brow = bias + (size_t)p * COUT;
    #pragma unroll
    for (int j = 0; j < 4; j++) {
        const int o0 = og + 8 * j + 2 * tig;
        float2 bb = *(const float2*)(brow + o0);
        #pragma unroll
        for (int b = 0; b < 2; b++) {
            float x0 = fmaf(acc[b][j][0], CORR2, bb.x);
            float x1 = fmaf(acc[b][j][1], CORR2, bb.y);
            float x2 = fmaf(acc[b][j][2], CORR2, bb.x);
            float x3 = fmaf(acc[b][j][3], CORR2, bb.y);
            x0 = (x0 > 0.0f) ? x0 : expm1f(x0);
            x1 = (x1 > 0.0f) ? x1 : expm1f(x1);
            x2 = (x2 > 0.0f) ? x2 : expm1f(x2);
            x3 = (x3 > 0.0f) ? x3 : expm1f(x3);
            acc[b][j][0] = C * x0; acc[b][j][1] = C * x1;
            acc[b][j][2] = C * x2; acc[b][j][3] = C * x3;
        }
    }
    __syncthreads();

    // residual GEMM accumulates in place (A1/W1 both rna tf32 — unbiased)
    slice_mma(aFrag + TB, aFrag + TB + aHalf, wFrag + TB, acc);

    // ---- store: out[b][p][o] with streaming stores (st.global.cs) ----
    #pragma unroll
    for (int j = 0; j < 4; j++) {
        const int o0 = og + 8 * j + 2 * tig;
        #pragma unroll
        for (int b = 0; b < 2; b++) {
            const int r0 = bg + 16 * b + g;
            float2 v0 = { acc[b][j][0], acc[b][j][1] };
            float2 v1 = { acc[b][j][2], acc[b][j][3] };
            __stcs((float2*)(out + ((size_t)r0       * OUT_PN + p) * COUT + o0), v0);
            __stcs((float2*)(out + ((size_t)(r0 + 8) * OUT_PN + p) * COUT + o0), v1);
        }
    }
}

extern "C" void kernel_launch(void* const* d_in, const int* in_sizes, int n_in,
                              void* d_out, int out_size)
{
    const float* in_pc = (const float*)d_in[0];
    const int*   nid   = (const int*)  d_in[1];
    const float* wts   = (const float*)d_in[2];
    const float* bias  = (const float*)d_in[3];
    const float* pnb   = (const float*)d_in[4];
    const float* wres  = (const float*)d_in[5];
    float* out = (float*)d_out;

    pconv_mma<<<OUT_PN, 128>>>(in_pc, nid, wts, bias, pnb, wres, out);
}